// round 1
// baseline (speedup 1.0000x reference)
#include <cuda_runtime.h>
#include <math.h>

#define NMODES 6400
#define MMAX 80
#define SETUP_THREADS 256
#define MODES_PER_THREAD (NMODES / SETUP_THREADS)   // 25

// Scratch (static device memory — no runtime allocation)
__device__ float4 gModes[NMODES];        // x=C, y=sigma*K, z=omega*K, w=cutoff(n-1)
__device__ int gV;                       // number of valid (compacted) modes
__device__ unsigned int gPeakBits;       // max |displacement| as float bits

// ---------------------------------------------------------------------------
// Helpers
// ---------------------------------------------------------------------------
__device__ __forceinline__ float softplusf(float x) {
    // jax.nn.softplus in fp32: log1p(exp(x)) with large-x passthrough
    return (x > 20.0f) ? x : log1pf(expf(x));
}

struct ModeOut {
    float C, sigK, thK, cutoff;
    int valid;
};

__device__ __forceinline__ ModeOut eval_mode(
    int i, float mu, float Dmu, float T0mu, float Ly, float xo, float yo)
{
    const float PI  = 3.14159265358979323846f;          // rounds to np.float32(pi)
    const float LX  = 0.5f;
    const float Kf  = (float)(1.0 / 44100.0);
    const float MAXOM = (float)(10000.0 * 2.0 * 3.141592653589793);
    const float MINOM = (float)(20.0 * 2.0 * 3.141592653589793);
    // ALPHA/BETA as double then cast, matching np.float32(...) in reference
    const double OM2   = 2.0 * 3.141592653589793 * 500.0;
    const double DOMSQ = OM2 * OM2;
    const double LN10T3 = 3.0 * 2.302585092994045684;
    const float ALPHA = (float)(LN10T3 / DOMSQ * (DOMSQ / 6.0));
    const float BETA  = (float)(LN10T3 / DOMSQ * (1.0 / 1.0 - 1.0 / 6.0));

    float m  = (float)(i / MMAX + 1);
    float nn = (float)(i % MMAX + 1);

    float t1 = (m * PI) / LX;
    float t2 = (nn * PI) / Ly;
    float g1 = t1 * t1 + t2 * t2;
    float w2 = T0mu * g1 + (Dmu * g1) * g1;
    w2 = fmaxf(w2, 0.0f);
    float omega = sqrtf(w2);

    ModeOut mo;
    mo.valid = (omega <= MAXOM) && (omega >= MINOM);

    float sigma = ALPHA + BETA * (omega * omega);

    float xi = 0.1f * LX;
    float yi = 0.1f * Ly;
    float in_w  = cosf(((xi * PI) * m) / LX) * cosf(((yi * PI) * nn) / Ly);
    float out_w = cosf(((xo * PI) * m) / LX) * cosf(((yo * PI) * nn) / Ly);

    float ms = 0.25f * mu * LX * Ly;
    float P  = out_w * in_w * (Kf * Kf) * expf(-sigma * Kf) / ms;

    float thK = omega * Kf;
    mo.C    = P / (sinf(thK) + 1e-8f);
    mo.sigK = sigma * Kf;
    mo.thK  = thK;
    // skip mode once sigK*(n-1) > 40 (term < e^-40 * C : negligible vs 1e-3 tol)
    mo.cutoff = 40.0f / mo.sigK;
    return mo;
}

// ---------------------------------------------------------------------------
// Kernel 1: per-mode precompute + deterministic compaction of valid modes
// ---------------------------------------------------------------------------
__global__ void setup_kernel(const float* __restrict__ pmu,
                             const float* __restrict__ pD,
                             const float* __restrict__ pT0,
                             const float* __restrict__ pLy,
                             const float* __restrict__ pxo,
                             const float* __restrict__ pyo)
{
    int t = threadIdx.x;

    float mu   = softplusf(pmu[0]) + 1e-4f;
    float Dmu  = softplusf(pD[0])  + 1e-4f;
    float T0mu = softplusf(pT0[0]) + 1e-4f;
    float Ly = 1.1f + (4.0f - 1.1f) * ((tanhf(pLy[0]) + 1.0f) * 0.5f);
    const float LX = 0.5f;
    float xo = 0.49f * LX + (1.0f - 0.49f) * LX * ((tanhf(pxo[0]) + 1.0f) * 0.5f);
    float yo = 0.51f * Ly + (1.0f - 0.51f) * Ly * ((tanhf(pyo[0]) + 1.0f) * 0.5f);

    int base = t * MODES_PER_THREAD;

    // Pass 1: count valid modes in this thread's chunk
    int cnt = 0;
    for (int j = 0; j < MODES_PER_THREAD; ++j) {
        ModeOut mo = eval_mode(base + j, mu, Dmu, T0mu, Ly, xo, yo);
        cnt += mo.valid;
    }

    // Block-wide inclusive scan (Hillis-Steele), deterministic
    __shared__ int sc[SETUP_THREADS];
    sc[t] = cnt;
    __syncthreads();
    for (int off = 1; off < SETUP_THREADS; off <<= 1) {
        int v = (t >= off) ? sc[t - off] : 0;
        __syncthreads();
        sc[t] += v;
        __syncthreads();
    }
    int ofs = sc[t] - cnt;
    if (t == SETUP_THREADS - 1) gV = sc[SETUP_THREADS - 1];
    if (t == 0) gPeakBits = 0u;

    // Pass 2: recompute and write compacted
    for (int j = 0; j < MODES_PER_THREAD; ++j) {
        ModeOut mo = eval_mode(base + j, mu, Dmu, T0mu, Ly, xo, yo);
        if (mo.valid) {
            gModes[ofs++] = make_float4(mo.C, mo.sigK, mo.thK, mo.cutoff);
        }
    }
}

// ---------------------------------------------------------------------------
// Kernel 2: main synthesis. Block = 32 samples x 8 mode partitions.
// ---------------------------------------------------------------------------
__global__ void __launch_bounds__(256) plate_kernel(float* __restrict__ out, int N)
{
    const int tx = threadIdx.x;          // sample lane (0..31)
    const int ty = threadIdx.y;          // mode partition (0..7)
    const int sample = blockIdx.x * 32 + tx;

    const int V = gV;
    const int chunk = (V + 7) >> 3;
    const int i0 = ty * chunk;
    const int i1 = min(V, i0 + chunk);

    const float nf  = (float)sample;
    const float nm1 = nf - 1.0f;
    // warp-uniform minimum (n-1) for dead-mode skip
    const float nm1_min = (float)(blockIdx.x * 32) - 1.0f;

    float acc = 0.0f;
    #pragma unroll 2
    for (int i = i0; i < i1; ++i) {
        float4 md = __ldg(&gModes[i]);           // warp-uniform -> L1 broadcast
        if (nm1_min < md.w) {                    // uniform branch: mode still audible
            float s = sinf(nf * md.z);           // libdevice fast path (<105615)
            float e = __expf(-md.y * nm1);
            acc = fmaf(md.x * e, s, acc);
        }
    }

    __shared__ float red[32 * 9];                // pad 9 -> conflict-free
    red[tx * 9 + ty] = acc;
    __syncthreads();

    if (ty == 0) {
        float v = 0.0f;
        #pragma unroll
        for (int k = 0; k < 8; ++k) v += red[tx * 9 + k];
        float av = fabsf(v);
        if (sample < N) out[sample] = v; else av = 0.0f;
        // warp max -> single atomic per block (order-independent => deterministic)
        #pragma unroll
        for (int o = 16; o > 0; o >>= 1)
            av = fmaxf(av, __shfl_xor_sync(0xFFFFFFFFu, av, o));
        if (tx == 0) atomicMax(&gPeakBits, __float_as_uint(av));
    }
}

// ---------------------------------------------------------------------------
// Kernel 3: normalize by peak
// ---------------------------------------------------------------------------
__global__ void scale_kernel(float* __restrict__ out, int N)
{
    int i = blockIdx.x * blockDim.x + threadIdx.x;
    if (i < N) {
        float peak = __uint_as_float(gPeakBits) + 1e-8f;
        out[i] = out[i] / peak;
    }
}

// ---------------------------------------------------------------------------
extern "C" void kernel_launch(void* const* d_in, const int* in_sizes, int n_in,
                              void* d_out, int out_size)
{
    const float* mu  = (const float*)d_in[0];
    const float* Dm  = (const float*)d_in[1];
    const float* T0m = (const float*)d_in[2];
    const float* Lyr = (const float*)d_in[3];
    const float* xor_ = (const float*)d_in[4];
    const float* yor_ = (const float*)d_in[5];
    // d_in[6] = num_samples (device scalar) == out_size; grid sized from out_size
    int N = out_size;
    float* out = (float*)d_out;

    setup_kernel<<<1, SETUP_THREADS>>>(mu, Dm, T0m, Lyr, xor_, yor_);

    dim3 blk(32, 8);
    int nb = (N + 31) / 32;
    plate_kernel<<<nb, blk>>>(out, N);

    scale_kernel<<<(N + 255) / 256, 256>>>(out, N);
}

// round 2
// speedup vs baseline: 5.8523x; 5.8523x over previous
#include <cuda_runtime.h>
#include <math.h>

#define NMODES 6400
#define MMAX 80
#define SCHUNK 64          // samples per block
#define SH 32              // SCHUNK/2 packed f32x2 accumulators

typedef unsigned long long u64;

// Static device scratch (no runtime allocation)
__device__ float4 gA[NMODES];        // {a2, -b2, C, cutoff(n-1)}
__device__ float4 gB[NMODES];        // {theta, sin(theta), cos(theta), sigK}
__device__ unsigned int gPeakBits;   // max |displacement| as float bits

// ---------------------------------------------------------------------------
// f32x2 packed helpers (Blackwell FFMA2 path, PTX-only)
// ---------------------------------------------------------------------------
__device__ __forceinline__ u64 pack2(float lo, float hi) {
    u64 r; asm("mov.b64 %0, {%1, %2};" : "=l"(r) : "f"(lo), "f"(hi)); return r;
}
__device__ __forceinline__ void unpack2(u64 v, float& lo, float& hi) {
    asm("mov.b64 {%0, %1}, %2;" : "=f"(lo), "=f"(hi) : "l"(v));
}
__device__ __forceinline__ u64 fma2(u64 a, u64 b, u64 c) {
    u64 d; asm("fma.rn.f32x2 %0, %1, %2, %3;" : "=l"(d) : "l"(a), "l"(b), "l"(c)); return d;
}
__device__ __forceinline__ u64 mul2(u64 a, u64 b) {
    u64 d; asm("mul.rn.f32x2 %0, %1, %2;" : "=l"(d) : "l"(a), "l"(b)); return d;
}
__device__ __forceinline__ u64 add2(u64 a, u64 b) {
    u64 d; asm("add.rn.f32x2 %0, %1, %2;" : "=l"(d) : "l"(a), "l"(b)); return d;
}

__device__ __forceinline__ float softplusf(float x) {
    return (x > 20.0f) ? x : log1pf(expf(x));
}

// ---------------------------------------------------------------------------
// Kernel 1: per-mode precompute (6400 threads). No compaction — invalid or
// fully-decayed modes are skipped cheaply in the main loop via cutoff.
// The omega/validity fp32 path is IDENTICAL to the R1 kernel (known-matching).
// ---------------------------------------------------------------------------
__global__ void setup_kernel(const float* __restrict__ pmu,
                             const float* __restrict__ pD,
                             const float* __restrict__ pT0,
                             const float* __restrict__ pLy,
                             const float* __restrict__ pxo,
                             const float* __restrict__ pyo)
{
    int i = blockIdx.x * blockDim.x + threadIdx.x;
    if (i >= NMODES) return;
    if (i == 0) gPeakBits = 0u;

    // scalars (redundant per-thread; broadcast loads)
    float mu   = softplusf(pmu[0]) + 1e-4f;
    float Dmu  = softplusf(pD[0])  + 1e-4f;
    float T0mu = softplusf(pT0[0]) + 1e-4f;
    float Ly = 1.1f + (4.0f - 1.1f) * ((tanhf(pLy[0]) + 1.0f) * 0.5f);
    const float LX = 0.5f;
    float xo = 0.49f * LX + (1.0f - 0.49f) * LX * ((tanhf(pxo[0]) + 1.0f) * 0.5f);
    float yo = 0.51f * Ly + (1.0f - 0.51f) * Ly * ((tanhf(pyo[0]) + 1.0f) * 0.5f);

    const float PI  = 3.14159265358979323846f;
    const float Kf  = (float)(1.0 / 44100.0);
    const float MAXOM = (float)(10000.0 * 2.0 * 3.141592653589793);
    const float MINOM = (float)(20.0 * 2.0 * 3.141592653589793);
    const double OM2   = 2.0 * 3.141592653589793 * 500.0;
    const double DOMSQ = OM2 * OM2;
    const double LN10T3 = 3.0 * 2.302585092994045684;
    const float ALPHA = (float)(LN10T3 / DOMSQ * (DOMSQ / 6.0));
    const float BETA  = (float)(LN10T3 / DOMSQ * (1.0 / 1.0 - 1.0 / 6.0));

    float m  = (float)(i / MMAX + 1);
    float nn = (float)(i % MMAX + 1);

    float t1 = (m * PI) / LX;
    float t2 = (nn * PI) / Ly;
    float g1 = t1 * t1 + t2 * t2;
    float w2 = T0mu * g1 + (Dmu * g1) * g1;
    w2 = fmaxf(w2, 0.0f);
    float omega = sqrtf(w2);

    int valid = (omega <= MAXOM) && (omega >= MINOM);
    float sigma = ALPHA + BETA * (omega * omega);

    float xi = 0.1f * LX;
    float yi = 0.1f * Ly;
    float in_w  = cosf(((xi * PI) * m) / LX) * cosf(((yi * PI) * nn) / Ly);
    float out_w = cosf(((xo * PI) * m) / LX) * cosf(((yo * PI) * nn) / Ly);

    float ms = 0.25f * mu * LX * Ly;
    float P  = out_w * in_w * (Kf * Kf) * expf(-sigma * Kf) / ms;

    float thK  = omega * Kf;
    float sigK = sigma * Kf;

    // high-precision recurrence coefficients (stride-2: y(n+2)=a2*y(n)-b2*y(n-2))
    double rd  = exp(-(double)sigK);
    double c2d = cos(2.0 * (double)thK);
    float a2  = (float)(2.0 * rd * rd * c2d);
    float nb2 = (float)(-(rd * rd * rd * rd));

    float sth = (float)sin((double)thK);
    float cth = (float)cos((double)thK);
    float C = P / (sth + 1e-8f);

    // mode contributes while sigK*(n-1) <= 20  (e^-20 ~ 2e-9: negligible)
    float cutoff = valid ? (20.0f / sigK) : -2.0f;

    gA[i] = make_float4(a2, nb2, C, cutoff);
    gB[i] = make_float4(thK, sth, cth, sigK);
}

// ---------------------------------------------------------------------------
// Kernel 2: main synthesis. One block per 64-sample chunk. 256 threads;
// each thread iterates modes (stride 256, coalesced float4 loads), runs the
// packed even/odd Chebyshev recurrence re-seeded from sincosf per chunk.
// ---------------------------------------------------------------------------
__global__ void __launch_bounds__(256) plate_kernel(float* __restrict__ out, int N)
{
    const int lane = threadIdx.x & 31;
    const int warp = threadIdx.x >> 5;
    const int n0   = blockIdx.x * SCHUNK;
    const float n0f  = (float)n0;
    const float n0m1 = n0f - 1.0f;

    u64 acc[SH];
    #pragma unroll
    for (int j = 0; j < SH; ++j) acc[j] = 0ull;

    #pragma unroll 1
    for (int i = threadIdx.x; i < NMODES; i += 256) {
        float4 A = gA[i];                  // {a2, -b2, C, cutoff}
        if (n0m1 <= A.w) {                 // mode still audible in this chunk
            float4 B = gB[i];              // {theta, sinθ, cosθ, sigK}
            float s0, c0;
            sincosf(n0f * B.x, &s0, &c0);  // accurate phase re-seed
            float E0   = __expf(-B.w * n0m1);       // envelope at sample n0
            float r    = __expf(-B.w);
            float rinv = __expf(B.w);

            float sp1 = fmaf(s0, B.z,  c0 * B.y);   // sin((n0+1)θ)
            float sm1 = fmaf(s0, B.z, -c0 * B.y);   // sin((n0-1)θ)
            float sm2 = fmaf(2.0f * B.z, sm1, -s0); // sin((n0-2)θ)

            float CE  = A.z * E0;
            float ye0 = CE * s0;                    // y(n0)
            float yo0 = CE * r * sp1;               // y(n0+1)
            float ym1 = CE * rinv * sm1;            // y(n0-1)
            float ym2 = CE * (rinv * rinv) * sm2;   // y(n0-2)

            u64 vc  = pack2(ye0, yo0);
            u64 vp  = pack2(ym2, ym1);
            u64 A2  = pack2(A.x, A.x);
            u64 nB2 = pack2(A.y, A.y);

            acc[0] = add2(acc[0], vc);
            #pragma unroll
            for (int j = 1; j < SH; ++j) {
                u64 mm = mul2(nB2, vp);
                u64 vn = fma2(A2, vc, mm);          // 2 samples / 2 instr
                vp = vc; vc = vn;
                acc[j] = add2(acc[j], vc);
            }
        }
    }

    // Warp transpose-reduce: 32 pair-slots x 32 lanes -> lane l owns slot l
    // (slot l = samples 2l, 2l+1). 31 exchange+add steps total.
    #pragma unroll
    for (int stage = 0; stage < 5; ++stage) {
        const int d = 16 >> stage;                  // 16,8,4,2,1
        const bool hi = (lane & d) != 0;
        #pragma unroll
        for (int j = 0; j < (16 >> stage); ++j) {
            const int m = 16 >> stage;
            u64 a_ = acc[j], b_ = acc[j + m];
            u64 send = hi ? a_ : b_;
            u64 keep = hi ? b_ : a_;
            u64 recv = __shfl_xor_sync(0xFFFFFFFFu, send, d);
            acc[j] = add2(keep, recv);
        }
    }

    // Combine 8 warps via shared memory; write out; fused peak reduction.
    __shared__ u64 sred[8][33];                     // pad -> conflict-free
    sred[warp][lane] = acc[0];
    __syncthreads();

    if (threadIdx.x < SCHUNK) {
        const int j = threadIdx.x;                  // sample offset in chunk
        const float* f = (const float*)sred;        // row stride = 66 floats
        float v = 0.0f;
        #pragma unroll
        for (int w = 0; w < 8; ++w) v += f[w * 66 + j];

        int sample = n0 + j;
        float av = fabsf(v);
        if (sample < N) out[sample] = v; else av = 0.0f;
        #pragma unroll
        for (int o = 16; o > 0; o >>= 1)
            av = fmaxf(av, __shfl_xor_sync(0xFFFFFFFFu, av, o));
        if (lane == 0) atomicMax(&gPeakBits, __float_as_uint(av));
    }
}

// ---------------------------------------------------------------------------
// Kernel 3: normalize by peak
// ---------------------------------------------------------------------------
__global__ void scale_kernel(float* __restrict__ out, int N)
{
    int i = blockIdx.x * blockDim.x + threadIdx.x;
    if (i < N) {
        float peak = __uint_as_float(gPeakBits) + 1e-8f;
        out[i] = out[i] / peak;
    }
}

// ---------------------------------------------------------------------------
extern "C" void kernel_launch(void* const* d_in, const int* in_sizes, int n_in,
                              void* d_out, int out_size)
{
    const float* mu  = (const float*)d_in[0];
    const float* Dm  = (const float*)d_in[1];
    const float* T0m = (const float*)d_in[2];
    const float* Lyr = (const float*)d_in[3];
    const float* xr  = (const float*)d_in[4];
    const float* yr  = (const float*)d_in[5];
    int N = out_size;                      // == num_samples
    float* out = (float*)d_out;

    setup_kernel<<<(NMODES + 255) / 256, 256>>>(mu, Dm, T0m, Lyr, xr, yr);

    int nb = (N + SCHUNK - 1) / SCHUNK;
    plate_kernel<<<nb, 256>>>(out, N);

    scale_kernel<<<(N + 255) / 256, 256>>>(out, N);
}

// round 3
// speedup vs baseline: 6.2096x; 1.0610x over previous
#include <cuda_runtime.h>
#include <math.h>

#define NMODES 6400
#define MMAX 80
#define GROUPS 25          // NMODES / 256
#define GSZ 256
#define SCHUNK 64          // samples per plate block
#define SH 32              // SCHUNK/2 packed f32x2 accumulators
#define NCB 2048           // max bucket count (chunks); N=44100 -> 690 chunks

typedef unsigned long long u64;

// ---------------- static device scratch (no runtime allocation) -------------
__device__ float4 gA0[NMODES], gB0[NMODES];   // staging (mode-index order)
__device__ float4 gA[NMODES],  gB[NMODES];    // sorted by lifetime desc
__device__ int    gLc[NMODES];                // live-chunk count per mode
__device__ int    gRank[NMODES];              // stable rank within (group,bucket)
__device__ int    gH[GROUPS][NCB];            // per-group bucket histograms
__device__ int    gBase[NCB];                 // bucket base = live count L(c)
__device__ unsigned int gPeakBits;

// ---------------- f32x2 packed helpers (Blackwell FFMA2 path) ---------------
__device__ __forceinline__ u64 pack2(float lo, float hi) {
    u64 r; asm("mov.b64 %0, {%1, %2};" : "=l"(r) : "f"(lo), "f"(hi)); return r;
}
__device__ __forceinline__ u64 fma2(u64 a, u64 b, u64 c) {
    u64 d; asm("fma.rn.f32x2 %0, %1, %2, %3;" : "=l"(d) : "l"(a), "l"(b), "l"(c)); return d;
}
__device__ __forceinline__ u64 mul2(u64 a, u64 b) {
    u64 d; asm("mul.rn.f32x2 %0, %1, %2;" : "=l"(d) : "l"(a), "l"(b)); return d;
}
__device__ __forceinline__ u64 add2(u64 a, u64 b) {
    u64 d; asm("add.rn.f32x2 %0, %1, %2;" : "=l"(d) : "l"(a), "l"(b)); return d;
}

__device__ __forceinline__ float softplusf(float x) {
    return (x > 20.0f) ? x : log1pf(expf(x));
}

// ---------------------------------------------------------------------------
// S1: per-mode precompute (all fp32) + bucket histogram + stable in-group rank
// grid = 25 blocks x 256
// ---------------------------------------------------------------------------
__global__ void __launch_bounds__(GSZ) s1_kernel(
    const float* __restrict__ pmu, const float* __restrict__ pD,
    const float* __restrict__ pT0, const float* __restrict__ pLy,
    const float* __restrict__ pxo, const float* __restrict__ pyo, int NC)
{
    const int g = blockIdx.x, t = threadIdx.x;
    const int i = g * GSZ + t;

    float mu   = softplusf(pmu[0]) + 1e-4f;
    float Dmu  = softplusf(pD[0])  + 1e-4f;
    float T0mu = softplusf(pT0[0]) + 1e-4f;
    float Ly = 1.1f + (4.0f - 1.1f) * ((tanhf(pLy[0]) + 1.0f) * 0.5f);
    const float LX = 0.5f;
    float xo = 0.49f * LX + (1.0f - 0.49f) * LX * ((tanhf(pxo[0]) + 1.0f) * 0.5f);
    float yo = 0.51f * Ly + (1.0f - 0.51f) * Ly * ((tanhf(pyo[0]) + 1.0f) * 0.5f);

    const float PI  = 3.14159265358979323846f;
    const float Kf  = (float)(1.0 / 44100.0);
    const float MAXOM = (float)(10000.0 * 2.0 * 3.141592653589793);
    const float MINOM = (float)(20.0 * 2.0 * 3.141592653589793);
    const double OM2   = 2.0 * 3.141592653589793 * 500.0;
    const double DOMSQ = OM2 * OM2;
    const double LN10T3 = 3.0 * 2.302585092994045684;
    const float ALPHA = (float)(LN10T3 / DOMSQ * (DOMSQ / 6.0));
    const float BETA  = (float)(LN10T3 / DOMSQ * (1.0 / 1.0 - 1.0 / 6.0));

    float m  = (float)(i / MMAX + 1);
    float nn = (float)(i % MMAX + 1);

    // omega / validity path identical (fp32) to the known-passing kernel
    float t1 = (m * PI) / LX;
    float t2 = (nn * PI) / Ly;
    float g1 = t1 * t1 + t2 * t2;
    float w2 = T0mu * g1 + (Dmu * g1) * g1;
    w2 = fmaxf(w2, 0.0f);
    float omega = sqrtf(w2);
    int valid = (omega <= MAXOM) && (omega >= MINOM);

    float sigma = ALPHA + BETA * (omega * omega);
    float xi = 0.1f * LX, yi = 0.1f * Ly;
    float in_w  = cosf(((xi * PI) * m) / LX) * cosf(((yi * PI) * nn) / Ly);
    float out_w = cosf(((xo * PI) * m) / LX) * cosf(((yo * PI) * nn) / Ly);
    float ms = 0.25f * mu * LX * Ly;
    float P  = out_w * in_w * (Kf * Kf) * expf(-sigma * Kf) / ms;

    float thK  = omega * Kf;
    float sigK = sigma * Kf;

    // fp32 recurrence coefficients (storage is fp32 anyway; same net rounding)
    float sth, cth;
    sincosf(thK, &sth, &cth);
    float r   = expf(-sigK);
    float r2  = r * r;
    float c2  = fmaf(-2.0f * sth, sth, 1.0f);   // cos(2*thK) = 1 - 2 sin^2
    float a2  = 2.0f * r2 * c2;
    float nb2 = -(r2 * r2);
    float C   = P / (sth + 1e-8f);

    // live while sigK*(n-1) <= 20  ->  live chunk count lc
    float cutoff = 20.0f / sigK;                // n-1 bound
    int lc = 0;
    if (valid) {
        lc = (int)floorf((cutoff + 1.0f) / 64.0f) + 1;   // chunk c live iff c < lc
        lc = max(0, min(lc, min(NC, NCB - 1)));
    }

    gA0[i] = make_float4(a2, nb2, C, cutoff);
    gB0[i] = make_float4(thK, sth, cth, sigK);
    gLc[i] = lc;

    // per-group histogram + stable rank within (group,bucket)
    __shared__ int sh_lc[GSZ];
    __shared__ int sh_h[NCB];
    for (int b = t; b < NCB; b += GSZ) sh_h[b] = 0;
    sh_lc[t] = lc;
    __syncthreads();
    atomicAdd(&sh_h[lc], 1);
    // stable rank: count earlier same-bucket modes in this group (deterministic)
    int rk = 0;
    for (int j = 0; j < t; ++j) rk += (sh_lc[j] == lc);
    gRank[i] = rk;
    __syncthreads();
    for (int b = t; b < NCB; b += GSZ) gH[g][b] = sh_h[b];
}

// ---------------------------------------------------------------------------
// S2: bucket totals -> suffix-sum bases (gBase[b] = #modes with lc > b = L(b))
// 1 block x 1024
// ---------------------------------------------------------------------------
__global__ void s2_kernel(int NC)
{
    __shared__ int tot[NCB];
    int t = threadIdx.x;
    int NB = min(NC, NCB - 1);                  // max bucket value
    for (int b = t; b <= NB; b += blockDim.x) {
        int s = 0;
        #pragma unroll
        for (int g = 0; g < GROUPS; ++g) s += gH[g][b];
        tot[b] = s;
    }
    __syncthreads();
    for (int b = t; b <= NB; b += blockDim.x) {
        int s = 0;
        for (int b2 = b + 1; b2 <= NB; ++b2) s += tot[b2];
        gBase[b] = s;                           // L(b) & descending-bucket base
    }
    if (t == 0) gPeakBits = 0u;
}

// ---------------------------------------------------------------------------
// S3: scatter to sorted order.  grid = 25 x 256
// ---------------------------------------------------------------------------
__global__ void __launch_bounds__(GSZ) s3_kernel()
{
    const int g = blockIdx.x, t = threadIdx.x;
    const int i = g * GSZ + t;
    int lc = gLc[i];
    int pos = gBase[lc] + gRank[i];             // bucket base (desc order)
    for (int g2 = 0; g2 < g; ++g2) pos += gH[g2][lc];
    gA[pos] = gA0[i];
    gB[pos] = gB0[i];
}

// ---------------------------------------------------------------------------
// Plate: one block per 64-sample chunk; loop over exactly the live modes.
// ---------------------------------------------------------------------------
__global__ void __launch_bounds__(256) plate_kernel(float* __restrict__ out, int N)
{
    const int lane = threadIdx.x & 31;
    const int warp = threadIdx.x >> 5;
    const int c    = blockIdx.x;
    const int n0   = c * SCHUNK;
    const float n0f  = (float)n0;
    const float n0m1 = n0f - 1.0f;
    const int Lc = gBase[c];                    // live modes = sorted prefix

    u64 acc[SH];
    #pragma unroll
    for (int j = 0; j < SH; ++j) acc[j] = 0ull;

    #pragma unroll 1
    for (int i = threadIdx.x; i < Lc; i += 256) {
        float4 A = gA[i];                       // {a2, -b2, C, cutoff}
        float4 B = gB[i];                       // {theta, sinθ, cosθ, sigK}
        float s0, c0;
        sincosf(n0f * B.x, &s0, &c0);           // accurate phase re-seed
        float E0   = __expf(-B.w * n0m1);
        float r    = __expf(-B.w);
        float rinv = __expf(B.w);

        float sp1 = fmaf(s0, B.z,  c0 * B.y);   // sin((n0+1)θ)
        float sm1 = fmaf(s0, B.z, -c0 * B.y);   // sin((n0-1)θ)
        float sm2 = fmaf(2.0f * B.z, sm1, -s0); // sin((n0-2)θ)

        float CE  = A.z * E0;
        float ye0 = CE * s0;
        float yo0 = CE * r * sp1;
        float ym1 = CE * rinv * sm1;
        float ym2 = CE * (rinv * rinv) * sm2;

        u64 vc  = pack2(ye0, yo0);
        u64 vp  = pack2(ym2, ym1);
        u64 A2  = pack2(A.x, A.x);
        u64 nB2 = pack2(A.y, A.y);

        acc[0] = add2(acc[0], vc);
        #pragma unroll
        for (int j = 1; j < SH; ++j) {
            u64 mm = mul2(nB2, vp);
            u64 vn = fma2(A2, vc, mm);          // stride-2 Chebyshev, 2 samp/2 op
            vp = vc; vc = vn;
            acc[j] = add2(acc[j], vc);
        }
    }

    // warp transpose-reduce: lane l ends owning sample pair (2l, 2l+1)
    #pragma unroll
    for (int stage = 0; stage < 5; ++stage) {
        const int d = 16 >> stage;
        const bool hi = (lane & d) != 0;
        #pragma unroll
        for (int j = 0; j < (16 >> stage); ++j) {
            const int m = 16 >> stage;
            u64 a_ = acc[j], b_ = acc[j + m];
            u64 send = hi ? a_ : b_;
            u64 keep = hi ? b_ : a_;
            u64 recv = __shfl_xor_sync(0xFFFFFFFFu, send, d);
            acc[j] = add2(keep, recv);
        }
    }

    __shared__ u64 sred[8][33];
    sred[warp][lane] = acc[0];
    __syncthreads();

    if (threadIdx.x < SCHUNK) {
        const int j = threadIdx.x;
        const float* f = (const float*)sred;    // row stride = 66 floats
        float v = 0.0f;
        #pragma unroll
        for (int w = 0; w < 8; ++w) v += f[w * 66 + j];

        int sample = n0 + j;
        float av = fabsf(v);
        if (sample < N) out[sample] = v; else av = 0.0f;
        #pragma unroll
        for (int o = 16; o > 0; o >>= 1)
            av = fmaxf(av, __shfl_xor_sync(0xFFFFFFFFu, av, o));
        if (lane == 0) atomicMax(&gPeakBits, __float_as_uint(av));
    }
}

// ---------------------------------------------------------------------------
__global__ void scale_kernel(float* __restrict__ out, int N)
{
    int i = blockIdx.x * blockDim.x + threadIdx.x;
    if (i < N) {
        float peak = __uint_as_float(gPeakBits) + 1e-8f;
        out[i] = out[i] / peak;
    }
}

// ---------------------------------------------------------------------------
extern "C" void kernel_launch(void* const* d_in, const int* in_sizes, int n_in,
                              void* d_out, int out_size)
{
    const float* mu  = (const float*)d_in[0];
    const float* Dm  = (const float*)d_in[1];
    const float* T0m = (const float*)d_in[2];
    const float* Lyr = (const float*)d_in[3];
    const float* xr  = (const float*)d_in[4];
    const float* yr  = (const float*)d_in[5];
    int N  = out_size;                          // == num_samples
    int NC = (N + SCHUNK - 1) / SCHUNK;
    float* out = (float*)d_out;

    s1_kernel<<<GROUPS, GSZ>>>(mu, Dm, T0m, Lyr, xr, yr, NC);
    s2_kernel<<<1, 1024>>>(NC);
    s3_kernel<<<GROUPS, GSZ>>>();
    plate_kernel<<<NC, 256>>>(out, N);
    scale_kernel<<<(N + 255) / 256, 256>>>(out, N);
}

// round 4
// speedup vs baseline: 7.1308x; 1.1484x over previous
#include <cuda_runtime.h>
#include <math.h>

#define NMODES 6400
#define MMAX 80
#define GROUPS 25          // NMODES / 256
#define GSZ 256
#define SCHUNK 64          // samples per plate block
#define SH 32              // SCHUNK/2 packed f32x2 accumulators
#define NCB 1024           // bucket table size (chunks); N=44100 -> 690 chunks

typedef unsigned long long u64;

// ---------------- static device scratch (no runtime allocation) -------------
__device__ float4 gA0[NMODES], gB0[NMODES];   // staging (mode-index order)
__device__ float4 gA[NMODES],  gB[NMODES];    // sorted by lifetime desc
__device__ int    gLc[NMODES];                // live-chunk count per mode
__device__ int    gRank[NMODES];              // deterministic rank in (group,bucket)
__device__ int    gH[GROUPS][NCB];            // per-group bucket histograms
__device__ int    gBase[NCB];                 // bucket base = live count L(c)
__device__ unsigned int gPeakBits;

// ---------------- f32x2 packed helpers (Blackwell FFMA2 path) ---------------
__device__ __forceinline__ u64 pack2(float lo, float hi) {
    u64 r; asm("mov.b64 %0, {%1, %2};" : "=l"(r) : "f"(lo), "f"(hi)); return r;
}
__device__ __forceinline__ u64 fma2(u64 a, u64 b, u64 c) {
    u64 d; asm("fma.rn.f32x2 %0, %1, %2, %3;" : "=l"(d) : "l"(a), "l"(b), "l"(c)); return d;
}
__device__ __forceinline__ u64 mul2(u64 a, u64 b) {
    u64 d; asm("mul.rn.f32x2 %0, %1, %2;" : "=l"(d) : "l"(a), "l"(b)); return d;
}
__device__ __forceinline__ u64 add2(u64 a, u64 b) {
    u64 d; asm("add.rn.f32x2 %0, %1, %2;" : "=l"(d) : "l"(a), "l"(b)); return d;
}

__device__ __forceinline__ float softplusf(float x) {
    return (x > 20.0f) ? x : log1pf(expf(x));
}

// ---------------------------------------------------------------------------
// S1: per-mode precompute (all fp32) + histogram + deterministic rank
// grid = 25 blocks x 256
// ---------------------------------------------------------------------------
__global__ void __launch_bounds__(GSZ) s1_kernel(
    const float* __restrict__ pmu, const float* __restrict__ pD,
    const float* __restrict__ pT0, const float* __restrict__ pLy,
    const float* __restrict__ pxo, const float* __restrict__ pyo, int NC)
{
    const int g = blockIdx.x, t = threadIdx.x;
    const int i = g * GSZ + t;
    const int warp = t >> 5, lane = t & 31;

    float mu   = softplusf(pmu[0]) + 1e-4f;
    float Dmu  = softplusf(pD[0])  + 1e-4f;
    float T0mu = softplusf(pT0[0]) + 1e-4f;
    float Ly = 1.1f + (4.0f - 1.1f) * ((tanhf(pLy[0]) + 1.0f) * 0.5f);
    const float LX = 0.5f;
    float xo = 0.49f * LX + (1.0f - 0.49f) * LX * ((tanhf(pxo[0]) + 1.0f) * 0.5f);
    float yo = 0.51f * Ly + (1.0f - 0.51f) * Ly * ((tanhf(pyo[0]) + 1.0f) * 0.5f);

    const float PI  = 3.14159265358979323846f;
    const float Kf  = (float)(1.0 / 44100.0);
    const float MAXOM = (float)(10000.0 * 2.0 * 3.141592653589793);
    const float MINOM = (float)(20.0 * 2.0 * 3.141592653589793);
    const double OM2   = 2.0 * 3.141592653589793 * 500.0;
    const double DOMSQ = OM2 * OM2;
    const double LN10T3 = 3.0 * 2.302585092994045684;
    const float ALPHA = (float)(LN10T3 / DOMSQ * (DOMSQ / 6.0));
    const float BETA  = (float)(LN10T3 / DOMSQ * (1.0 / 1.0 - 1.0 / 6.0));

    float m  = (float)(i / MMAX + 1);
    float nn = (float)(i % MMAX + 1);

    // omega / validity path identical (fp32) to the known-passing kernel
    float t1 = (m * PI) / LX;
    float t2 = (nn * PI) / Ly;
    float g1 = t1 * t1 + t2 * t2;
    float w2 = T0mu * g1 + (Dmu * g1) * g1;
    w2 = fmaxf(w2, 0.0f);
    float omega = sqrtf(w2);
    int valid = (omega <= MAXOM) && (omega >= MINOM);

    float sigma = ALPHA + BETA * (omega * omega);
    float xi = 0.1f * LX, yi = 0.1f * Ly;
    float in_w  = cosf(((xi * PI) * m) / LX) * cosf(((yi * PI) * nn) / Ly);
    float out_w = cosf(((xo * PI) * m) / LX) * cosf(((yo * PI) * nn) / Ly);
    float ms = 0.25f * mu * LX * Ly;
    float P  = out_w * in_w * (Kf * Kf) * expf(-sigma * Kf) / ms;

    float thK  = omega * Kf;
    float sigK = sigma * Kf;

    float sth, cth;
    sincosf(thK, &sth, &cth);
    float r   = expf(-sigK);
    float r2  = r * r;
    float c2  = fmaf(-2.0f * sth, sth, 1.0f);   // cos(2*thK) = 1 - 2 sin^2
    float a2  = 2.0f * r2 * c2;
    float nb2 = -(r2 * r2);
    float C   = P / (sth + 1e-8f);

    // live while sigK*(n-1) <= 20  ->  live chunk count lc
    float cutoff = 20.0f / sigK;
    int lc = 0;
    if (valid) {
        lc = (int)floorf((cutoff + 1.0f) / 64.0f) + 1;
        lc = max(0, min(lc, min(NC, NCB - 1)));
    }

    gA0[i] = make_float4(a2, nb2, C, cutoff);
    gB0[i] = make_float4(thK, sth, cth, sigK);
    gLc[i] = lc;

    // deterministic rank within (group,bucket): match-any within warp,
    // fixed warp order across warps (one shared atomic per (warp,bucket))
    __shared__ int sh_h[NCB];
    for (int b = t; b < NCB; b += GSZ) sh_h[b] = 0;
    __syncthreads();

    unsigned msk = __match_any_sync(0xFFFFFFFFu, lc);
    int riw    = __popc(msk & ((1u << lane) - 1u));
    int leader = __ffs(msk) - 1;
    int cnt    = __popc(msk);
    int rk = 0;
    #pragma unroll
    for (int w = 0; w < 8; ++w) {
        if (warp == w) {
            int base = 0;
            if (lane == leader) base = atomicAdd(&sh_h[lc], cnt);
            base = __shfl_sync(0xFFFFFFFFu, base, leader);
            rk = base + riw;
        }
        __syncthreads();
    }
    gRank[i] = rk;
    for (int b = t; b < NCB; b += GSZ) gH[g][b] = sh_h[b];
}

// ---------------------------------------------------------------------------
// S2: bucket totals -> suffix sums via reversed Hillis-Steele scan.
// gBase[b] = #modes with lc > b = live count L(b).  1 block x 1024.
// ---------------------------------------------------------------------------
__global__ void __launch_bounds__(NCB) s2_kernel(int NC)
{
    __shared__ int incl[NCB];
    __shared__ int orig[NCB];
    const int t = threadIdx.x;
    const int NB = min(NC, NCB - 1);            // max bucket index
    const int b = NB - t;                       // reversed mapping

    int s = 0;
    if (b >= 0) {
        #pragma unroll
        for (int g = 0; g < GROUPS; ++g) s += gH[g][b];
    }
    incl[t] = s; orig[t] = s;
    __syncthreads();

    for (int off = 1; off <= NB; off <<= 1) {
        int v = (t >= off && t <= NB) ? incl[t - off] : 0;
        __syncthreads();
        if (t <= NB) incl[t] += v;
        __syncthreads();
    }
    if (b >= 0) gBase[b] = incl[t] - orig[t];   // strict suffix sum
    if (t == 0) gPeakBits = 0u;
}

// ---------------------------------------------------------------------------
// S3: scatter to lifetime-descending order.  grid = 25 x 256
// ---------------------------------------------------------------------------
__global__ void __launch_bounds__(GSZ) s3_kernel()
{
    const int g = blockIdx.x, t = threadIdx.x;
    const int i = g * GSZ + t;
    int lc = gLc[i];
    int pos = gBase[lc] + gRank[i];
    for (int g2 = 0; g2 < g; ++g2) pos += gH[g2][lc];
    gA[pos] = gA0[i];
    gB[pos] = gB0[i];
}

// ---------------------------------------------------------------------------
// Plate: one block per 64-sample chunk; exactly the live modes (sorted
// prefix). TWO independent mode chains per thread for FMA-latency ILP.
// ---------------------------------------------------------------------------
struct Chain { u64 vc, vp, A2, nB2; };

__device__ __forceinline__ Chain seed_chain(float4 A, float4 B,
                                            float n0f, float n0m1, bool on)
{
    float s0, c0;
    sincosf(n0f * B.x, &s0, &c0);               // accurate phase re-seed
    float E0   = __expf(-B.w * n0m1);
    float r    = __expf(-B.w);
    float rinv = __expf(B.w);

    float sp1 = fmaf(s0, B.z,  c0 * B.y);       // sin((n0+1)θ)
    float sm1 = fmaf(s0, B.z, -c0 * B.y);       // sin((n0-1)θ)
    float sm2 = fmaf(2.0f * B.z, sm1, -s0);     // sin((n0-2)θ)

    float CE = on ? (A.z * E0) : 0.0f;
    Chain ch;
    ch.vc  = pack2(CE * s0, CE * r * sp1);              // y(n0),  y(n0+1)
    ch.vp  = pack2(CE * (rinv * rinv) * sm2, CE * rinv * sm1); // y(n0-2), y(n0-1)
    ch.A2  = pack2(A.x, A.x);
    ch.nB2 = pack2(A.y, A.y);
    return ch;
}

__global__ void __launch_bounds__(256, 2) plate_kernel(float* __restrict__ out, int N)
{
    const int lane = threadIdx.x & 31;
    const int warp = threadIdx.x >> 5;
    const int c    = blockIdx.x;
    const int n0   = c * SCHUNK;
    const float n0f  = (float)n0;
    const float n0m1 = n0f - 1.0f;
    const int Lc = gBase[c];                    // live modes = sorted prefix

    u64 acc[SH];
    #pragma unroll
    for (int j = 0; j < SH; ++j) acc[j] = 0ull;

    #pragma unroll 1
    for (int i = threadIdx.x; i < Lc; i += 512) {
        int ib = i + 256;
        bool ok2 = ib < Lc;
        int i2 = ok2 ? ib : i;                  // duplicate w/ CE=0 if past end

        float4 Aa = gA[i],  Ba = gB[i];
        float4 Ab = gA[i2], Bb = gB[i2];

        Chain ca = seed_chain(Aa, Ba, n0f, n0m1, true);
        Chain cb = seed_chain(Ab, Bb, n0f, n0m1, ok2);

        acc[0] = add2(add2(acc[0], ca.vc), cb.vc);
        #pragma unroll
        for (int j = 1; j < SH; ++j) {
            u64 ma = mul2(ca.nB2, ca.vp);
            u64 mb = mul2(cb.nB2, cb.vp);
            u64 na = fma2(ca.A2, ca.vc, ma);    // two independent chains
            u64 nb = fma2(cb.A2, cb.vc, mb);
            ca.vp = ca.vc; ca.vc = na;
            cb.vp = cb.vc; cb.vc = nb;
            acc[j] = add2(add2(acc[j], na), nb);
        }
    }

    // warp transpose-reduce: lane l ends owning sample pair (2l, 2l+1)
    #pragma unroll
    for (int stage = 0; stage < 5; ++stage) {
        const int d = 16 >> stage;
        const bool hi = (lane & d) != 0;
        #pragma unroll
        for (int j = 0; j < (16 >> stage); ++j) {
            const int mm = 16 >> stage;
            u64 a_ = acc[j], b_ = acc[j + mm];
            u64 send = hi ? a_ : b_;
            u64 keep = hi ? b_ : a_;
            u64 recv = __shfl_xor_sync(0xFFFFFFFFu, send, d);
            acc[j] = add2(keep, recv);
        }
    }

    __shared__ u64 sred[8][33];
    sred[warp][lane] = acc[0];
    __syncthreads();

    if (threadIdx.x < SCHUNK) {
        const int j = threadIdx.x;
        const float* f = (const float*)sred;    // row stride = 66 floats
        float v = 0.0f;
        #pragma unroll
        for (int w = 0; w < 8; ++w) v += f[w * 66 + j];

        int sample = n0 + j;
        float av = fabsf(v);
        if (sample < N) out[sample] = v; else av = 0.0f;
        #pragma unroll
        for (int o = 16; o > 0; o >>= 1)
            av = fmaxf(av, __shfl_xor_sync(0xFFFFFFFFu, av, o));
        if (lane == 0) atomicMax(&gPeakBits, __float_as_uint(av));
    }
}

// ---------------------------------------------------------------------------
__global__ void scale_kernel(float* __restrict__ out, int N)
{
    int i = blockIdx.x * blockDim.x + threadIdx.x;
    if (i < N) {
        float peak = __uint_as_float(gPeakBits) + 1e-8f;
        out[i] = out[i] / peak;
    }
}

// ---------------------------------------------------------------------------
extern "C" void kernel_launch(void* const* d_in, const int* in_sizes, int n_in,
                              void* d_out, int out_size)
{
    const float* mu  = (const float*)d_in[0];
    const float* Dm  = (const float*)d_in[1];
    const float* T0m = (const float*)d_in[2];
    const float* Lyr = (const float*)d_in[3];
    const float* xr  = (const float*)d_in[4];
    const float* yr  = (const float*)d_in[5];
    int N  = out_size;                          // == num_samples
    int NC = (N + SCHUNK - 1) / SCHUNK;
    float* out = (float*)d_out;

    s1_kernel<<<GROUPS, GSZ>>>(mu, Dm, T0m, Lyr, xr, yr, NC);
    s2_kernel<<<1, NCB>>>(NC);
    s3_kernel<<<GROUPS, GSZ>>>();
    plate_kernel<<<NC, 256>>>(out, N);
    scale_kernel<<<(N + 255) / 256, 256>>>(out, N);
}